// round 16
// baseline (speedup 1.0000x reference)
#include <cuda_runtime.h>
#include <cuda_fp16.h>
#include <cstdint>

#define MAXN 100000
#define MAXE 1600000

// ---------------- scratch (device globals; allocation-free) ----------------
__device__ __align__(16) __half g_xh[MAXN * 128];
__device__ __align__(16) __half g_w1h[128 * 128];
__device__ __align__(16) __half g_w2h[128 * 64];
__device__ __align__(16) __half g_h1h[MAXN * 128];
__device__ __align__(16) __half g_z1h[MAXN * 128];
__device__ __align__(16) __half g_h2h[MAXN * 64];
__device__ __align__(16) float g_z2[MAXN * 64];
__device__ __align__(8) float g_as1[MAXN * 2];
__device__ __align__(8) float g_ad1[MAXN * 2];
__device__ float g_as2[MAXN];
__device__ float g_ad2[MAXN];
__device__ __align__(16) int4 g_epk[MAXE + MAXN];
__device__ int g_deg[MAXN];          // zero at load; re-zeroed each scan
__device__ int g_rowstart[MAXN + 1];
__device__ int g_cursor[MAXN];
__device__ int g_part[128];
__device__ int g_ctr;                // scan barrier counter (reset by misc kernel)

// ---------------- helpers ----------------
__device__ __forceinline__ uint32_t smem_u32(const void* p) {
    uint32_t a;
    asm("{ .reg .u64 t; cvta.to.shared.u64 t, %1; cvt.u32.u64 %0, t; }" : "=r"(a) : "l"(p));
    return a;
}
__device__ __forceinline__ void ldsm4(uint32_t& r0, uint32_t& r1, uint32_t& r2, uint32_t& r3,
                                      uint32_t addr) {
    asm volatile("ldmatrix.sync.aligned.m8n8.x4.shared.b16 {%0,%1,%2,%3}, [%4];"
                 : "=r"(r0), "=r"(r1), "=r"(r2), "=r"(r3) : "r"(addr));
}
__device__ __forceinline__ void ldsm4t(uint32_t& r0, uint32_t& r1, uint32_t& r2, uint32_t& r3,
                                       uint32_t addr) {
    asm volatile("ldmatrix.sync.aligned.m8n8.x4.trans.shared.b16 {%0,%1,%2,%3}, [%4];"
                 : "=r"(r0), "=r"(r1), "=r"(r2), "=r"(r3) : "r"(addr));
}
__device__ __forceinline__ void mma16816(float* c, const uint32_t* a, const uint32_t* b) {
    asm volatile(
        "mma.sync.aligned.m16n8k16.row.col.f32.f16.f16.f32 "
        "{%0,%1,%2,%3}, {%4,%5,%6,%7}, {%8,%9}, {%0,%1,%2,%3};"
        : "+f"(c[0]), "+f"(c[1]), "+f"(c[2]), "+f"(c[3])
        : "r"(a[0]), "r"(a[1]), "r"(a[2]), "r"(a[3]), "r"(b[0]), "r"(b[1]));
}
__device__ __forceinline__ void cp_async16(uint32_t smem_addr, const void* gptr, bool valid) {
    int sz = valid ? 16 : 0;
    asm volatile("cp.async.ca.shared.global [%0], [%1], 16, %2;"
                 :: "r"(smem_addr), "l"(gptr), "r"(sz));
}

// ------- fused misc: blocks [0,cvb) cvt x/W1/W2 -> fp16 ; blocks [cvb,..) hist -------
__global__ void misc_kernel(const float* __restrict__ x, const float* __restrict__ W1,
                            const float* __restrict__ W2,
                            const int* __restrict__ edst, int E, int N, int cvb) {
    int tid = threadIdx.x;
    if (blockIdx.x == 0 && tid == 0) g_ctr = 0;   // reset scan barrier for next launch
    if (blockIdx.x < cvb) {
        int nx = N * 128;
        int i = (blockIdx.x * blockDim.x + tid) * 8;
        int total = nx + 128 * 128 + 128 * 64;
        if (i >= total) return;
        const float* src;
        __half* dst;
        int off;
        if (i < nx)                  { src = x;  dst = g_xh;  off = i; }
        else if (i < nx + 128 * 128) { src = W1; dst = g_w1h; off = i - nx; }
        else                         { src = W2; dst = g_w2h; off = i - nx - 128 * 128; }
        float4 v0 = *(const float4*)&src[off];
        float4 v1 = *(const float4*)&src[off + 4];
        __half h[8];
        h[0] = __float2half_rn(v0.x); h[1] = __float2half_rn(v0.y);
        h[2] = __float2half_rn(v0.z); h[3] = __float2half_rn(v0.w);
        h[4] = __float2half_rn(v1.x); h[5] = __float2half_rn(v1.y);
        h[6] = __float2half_rn(v1.z); h[7] = __float2half_rn(v1.w);
        *(uint4*)&dst[off] = *(uint4*)h;
        return;
    }
    int t = (blockIdx.x - cvb) * blockDim.x + tid;
    if (t >= E + N) return;
    int dst = (t < E) ? edst[t] : (t - E);
    atomicAdd(&g_deg[dst], 1);
}

// ------- single-pass scan: block scan + grid barrier + look-back (nb <= 98 resident) -------
__global__ void scan_kernel(int N, int total, int nb) {
    __shared__ int sm[1024];
    __shared__ int sred[9];
    int tid = threadIdx.x;
    int i = blockIdx.x * 1024 + tid;
    int v = (i < N) ? g_deg[i] : 0;
    sm[tid] = v;
    __syncthreads();
#pragma unroll
    for (int o = 1; o < 1024; o <<= 1) {
        int t = 0;
        if (tid >= o) t = sm[tid - o];
        __syncthreads();
        if (tid >= o) sm[tid] += t;
        __syncthreads();
    }
    if (tid == 1023) {
        g_part[blockIdx.x] = sm[1023];
        __threadfence();
        atomicAdd(&g_ctr, 1);
    }
    if (tid == 0) {
        while (*(volatile int*)&g_ctr < nb) { }
    }
    __syncthreads();
    // parallel look-back: sum parts[0 .. blockIdx.x-1]
    if (tid < 128) {
        int pv = (tid < blockIdx.x) ? *(volatile int*)&g_part[tid] : 0;
#pragma unroll
        for (int o = 16; o; o >>= 1) pv += __shfl_down_sync(0xffffffffu, pv, o);
        if ((tid & 31) == 0) sred[tid >> 5] = pv;
    }
    __syncthreads();
    if (tid == 0) sred[8] = sred[0] + sred[1] + sred[2] + sred[3];
    __syncthreads();
    int prefix = sred[8];
    if (i < N) {
        int r = prefix + sm[tid] - v;
        g_rowstart[i] = r;
        g_cursor[i] = r;
        g_deg[i] = 0;
    }
    if (i == 0) g_rowstart[N] = total;
}

__global__ void scatter_kernel(const int* __restrict__ esrc, const int* __restrict__ edst,
                               int E, int N) {
    int t = blockIdx.x * blockDim.x + threadIdx.x;
    if (t >= E + N) return;
    int src, dst;
    if (t < E) { src = esrc[t]; dst = edst[t]; }
    else       { src = dst = t - E; }
    int pos = atomicAdd(&g_cursor[dst], 1);
    float2 as = *(const float2*)&g_as1[src * 2];
    float2 ad = *(const float2*)&g_ad1[dst * 2];
    float v0 = as.x + ad.x, v1 = as.y + ad.y;
    v0 = v0 > 0.f ? v0 : 0.2f * v0;
    v1 = v1 > 0.f ? v1 : 0.2f * v1;
    g_epk[pos] = make_int4(src, __float_as_int(__expf(v0)), __float_as_int(__expf(v1)), 0);
}

// ------- persistent tensor-core GEMM + alpha, 2x4 warp grid (from R15) -------
template <int NC>
__global__ void __launch_bounds__(256, 3)
mma_gemm_alpha_kernel(const __half* __restrict__ Xh, const __half* __restrict__ Wh,
                      __half* __restrict__ Y,
                      const float* __restrict__ av_s, const float* __restrict__ av_d,
                      float* __restrict__ out_s, float* __restrict__ out_d,
                      int N, int ntiles) {
    extern __shared__ __half hsm[];
    constexpr int LDA = 136;
    constexpr int LDB = NC + 8;
    constexpr int NH = (NC == 128) ? 2 : 1;
    __half* Abuf[2] = { hsm, hsm + 64 * LDA };
    __half* Bs = hsm + 128 * LDA;
    float* sS = (float*)(Bs + 128 * LDB);
    float* sD = sS + 64 * NH;
    const int tid = threadIdx.x;
    constexpr int NT = NC / 32;
    constexpr int NSTRIP = (NC / 4) / 16;

    int t0 = blockIdx.x;
    if (t0 < ntiles) {
        int row0 = t0 * 64;
        for (int i = tid * 8; i < 64 * 128; i += 2048) {
            int r = i >> 7, c = i & 127;
            int gr = row0 + r;
            cp_async16(smem_u32(&Abuf[0][r * LDA + c]), Xh + (size_t)gr * 128 + c, gr < N);
        }
        asm volatile("cp.async.commit_group;");
    }
    for (int i = tid * 8; i < 128 * NC; i += 2048) {
        int r = i / NC, c = i % NC;
        *(uint4*)&Bs[r * LDB + c] = *(const uint4*)&Wh[i];
    }

    const int lane = tid & 31, wid = tid >> 5;
    const int wr = wid & 1;
    const int wcg = wid >> 1;
    const int r_base = wr * 32;
    const int c_base = wcg * (NC / 4);
    const int head = (NC == 128) ? (wcg >> 1) : 0;
    const int lr = lane & 15, lh = lane >> 4;
    const int row_in = lane >> 2;
    const int qc = (lane & 3) * 2;
    const uint32_t b_base = smem_u32(Bs);

    int it = 0;
    for (int j = t0; j < ntiles; j += gridDim.x, it++) {
        int jn = j + gridDim.x;
        __half* Acur = Abuf[it & 1];
        if (jn < ntiles) {
            __half* Anxt = Abuf[(it + 1) & 1];
            int row0n = jn * 64;
            for (int i = tid * 8; i < 64 * 128; i += 2048) {
                int r = i >> 7, c = i & 127;
                int gr = row0n + r;
                cp_async16(smem_u32(&Anxt[r * LDA + c]), Xh + (size_t)gr * 128 + c, gr < N);
            }
            asm volatile("cp.async.commit_group;");
            asm volatile("cp.async.wait_group 1;");
        } else {
            asm volatile("cp.async.wait_group 0;");
        }
        if (tid < 64 * NH) { sS[tid] = 0.f; sD[tid] = 0.f; }
        __syncthreads();

        const int row0 = j * 64;
        float c[2][NT][4];
#pragma unroll
        for (int mt = 0; mt < 2; mt++)
#pragma unroll
            for (int nt = 0; nt < NT; nt++)
#pragma unroll
                for (int q = 0; q < 4; q++) c[mt][nt][q] = 0.f;

        const uint32_t a_base = smem_u32(Acur);
#pragma unroll
        for (int kk = 0; kk < 8; kk++) {
            int k0 = kk * 16;
            uint32_t a[2][4];
#pragma unroll
            for (int mt = 0; mt < 2; mt++) {
                uint32_t addr = a_base + ((r_base + mt * 16 + lr) * LDA + k0 + lh * 8) * 2;
                ldsm4(a[mt][0], a[mt][1], a[mt][2], a[mt][3], addr);
            }
            uint32_t b[NT][2];
#pragma unroll
            for (int s = 0; s < NSTRIP; s++) {
                int n0 = c_base + s * 16;
                uint32_t addr = b_base + ((k0 + lr) * LDB + n0 + lh * 8) * 2;
                uint32_t r0, r1, r2, r3;
                ldsm4t(r0, r1, r2, r3, addr);
                b[2 * s][0] = r0; b[2 * s][1] = r1;
                b[2 * s + 1][0] = r2; b[2 * s + 1][1] = r3;
            }
#pragma unroll
            for (int mt = 0; mt < 2; mt++)
#pragma unroll
                for (int nt = 0; nt < NT; nt++) mma16816(c[mt][nt], a[mt], b[nt]);
        }

#pragma unroll
        for (int mt = 0; mt < 2; mt++) {
            int gr0 = row0 + r_base + mt * 16 + row_in;
            int gr1 = gr0 + 8;
            float ps0 = 0.f, pd0 = 0.f, ps1 = 0.f, pd1 = 0.f;
#pragma unroll
            for (int nt = 0; nt < NT; nt++) {
                int col = c_base + nt * 8 + qc;
                float avs0 = av_s[col], avs1 = av_s[col + 1];
                float avd0 = av_d[col], avd1 = av_d[col + 1];
                float* cc = c[mt][nt];
                ps0 = fmaf(cc[0], avs0, fmaf(cc[1], avs1, ps0));
                pd0 = fmaf(cc[0], avd0, fmaf(cc[1], avd1, pd0));
                ps1 = fmaf(cc[2], avs0, fmaf(cc[3], avs1, ps1));
                pd1 = fmaf(cc[2], avd0, fmaf(cc[3], avd1, pd1));
                if (gr0 < N) *(__half2*)&Y[(size_t)gr0 * NC + col] = __floats2half2_rn(cc[0], cc[1]);
                if (gr1 < N) *(__half2*)&Y[(size_t)gr1 * NC + col] = __floats2half2_rn(cc[2], cc[3]);
            }
#pragma unroll
            for (int o = 1; o <= 2; o <<= 1) {
                ps0 += __shfl_xor_sync(0xffffffffu, ps0, o);
                pd0 += __shfl_xor_sync(0xffffffffu, pd0, o);
                ps1 += __shfl_xor_sync(0xffffffffu, ps1, o);
                pd1 += __shfl_xor_sync(0xffffffffu, pd1, o);
            }
            if ((lane & 3) == 0) {
                int rl0 = (r_base + mt * 16 + row_in) * NH + head;
                int rl1 = rl0 + 8 * NH;
                atomicAdd(&sS[rl0], ps0);
                atomicAdd(&sD[rl0], pd0);
                atomicAdd(&sS[rl1], ps1);
                atomicAdd(&sD[rl1], pd1);
            }
        }
        __syncthreads();
        if (tid < 64 * NH) {
            int gr = row0 + tid / NH;
            if (gr < N) {
                out_s[(size_t)gr * NH + (tid % NH)] = sS[tid];
                out_d[(size_t)gr * NH + (tid % NH)] = sD[tid];
            }
        }
        __syncthreads();
    }
}

// ---------------- layer1 aggregate: predicated loads (no wasted tail traffic) ----------------
__global__ void agg1_kernel(const float* __restrict__ b1, int N) {
    int w = blockIdx.x * 8 + (threadIdx.x >> 5);
    int lane = threadIdx.x & 31;
    if (w >= N) return;
    int s0 = g_rowstart[w], s1 = g_rowstart[w + 1];
    const int half = lane >> 4;
    const int fl = lane & 15;
    const bool h1sel = (fl >= 8);
    float acc[8];
#pragma unroll
    for (int k = 0; k < 8; k++) acc[k] = 0.f;
    float den0 = 0.f, den1 = 0.f;

    for (int base = s0; base < s1; base += 8) {
        int4 pk[4];
        bool vq[4];
#pragma unroll
        for (int q = 0; q < 4; q++) {
            int e = base + 2 * q + half;
            vq[q] = e < s1;
            pk[q] = make_int4(0, 0, 0, 0);
            if (vq[q]) pk[q] = g_epk[e];
        }
        uint4 uq[4];
#pragma unroll
        for (int q = 0; q < 4; q++) {
            uq[q] = make_uint4(0, 0, 0, 0);
            if (vq[q]) uq[q] = ((const uint4*)(g_h1h + (size_t)pk[q].x * 128))[fl];
        }
#pragma unroll
        for (int q = 0; q < 4; q++) {
            float e0 = __int_as_float(pk[q].y);
            float e1 = __int_as_float(pk[q].z);
            den0 += e0; den1 += e1;
            float a = h1sel ? e1 : e0;
            __half2* ph = (__half2*)&uq[q];
#pragma unroll
            for (int p = 0; p < 4; p++) {
                float2 f = __half22float2(ph[p]);
                acc[2 * p]     = fmaf(a, f.x, acc[2 * p]);
                acc[2 * p + 1] = fmaf(a, f.y, acc[2 * p + 1]);
            }
        }
    }
#pragma unroll
    for (int k = 0; k < 8; k++) acc[k] += __shfl_xor_sync(0xffffffffu, acc[k], 16);
    den0 += __shfl_xor_sync(0xffffffffu, den0, 16);
    den1 += __shfl_xor_sync(0xffffffffu, den1, 16);
    if (half == 0) {
        float rden = 1.f / (h1sel ? den1 : den0);
        __half hb[8];
#pragma unroll
        for (int k = 0; k < 8; k++) {
            float v = acc[k] * rden + b1[fl * 8 + k];
            v = v > 0.f ? v : (__expf(v) - 1.f);
            hb[k] = __float2half_rn(v);
        }
        *(uint4*)&g_z1h[(size_t)w * 128 + fl * 8] = *(uint4*)hb;
    }
}

// ---------------- layer2 aggregate: predicated loads ----------------
__global__ void agg2_kernel(const float* __restrict__ b2, int N) {
    int w = blockIdx.x * 8 + (threadIdx.x >> 5);
    int lane = threadIdx.x & 31;
    if (w >= N) return;
    int s0 = g_rowstart[w], s1 = g_rowstart[w + 1];
    float add_d = g_ad2[w];
    const int half = lane >> 4;
    const int fl = lane & 15;
    float4 acc = make_float4(0.f, 0.f, 0.f, 0.f);
    float den = 0.f;

    for (int base = s0; base < s1; base += 8) {
        int sq[4];
        bool vq[4];
#pragma unroll
        for (int q = 0; q < 4; q++) {
            int e = base + 2 * q + half;
            vq[q] = e < s1;
            sq[q] = 0;
            if (vq[q]) sq[q] = g_epk[e].x;
        }
        float asq[4];
#pragma unroll
        for (int q = 0; q < 4; q++) {
            asq[q] = 0.f;
            if (vq[q]) asq[q] = g_as2[sq[q]];
        }
        uint2 uq[4];
#pragma unroll
        for (int q = 0; q < 4; q++) {
            uq[q] = make_uint2(0, 0);
            if (vq[q]) uq[q] = ((const uint2*)(g_h2h + (size_t)sq[q] * 64))[fl];
        }
#pragma unroll
        for (int q = 0; q < 4; q++) {
            float v = asq[q] + add_d;
            v = v > 0.f ? v : 0.2f * v;
            float a = vq[q] ? __expf(v) : 0.f;
            den += a;
            __half2* ph = (__half2*)&uq[q];
            float2 f0 = __half22float2(ph[0]);
            float2 f1 = __half22float2(ph[1]);
            acc.x = fmaf(a, f0.x, acc.x);
            acc.y = fmaf(a, f0.y, acc.y);
            acc.z = fmaf(a, f1.x, acc.z);
            acc.w = fmaf(a, f1.y, acc.w);
        }
    }
    acc.x += __shfl_xor_sync(0xffffffffu, acc.x, 16);
    acc.y += __shfl_xor_sync(0xffffffffu, acc.y, 16);
    acc.z += __shfl_xor_sync(0xffffffffu, acc.z, 16);
    acc.w += __shfl_xor_sync(0xffffffffu, acc.w, 16);
    den += __shfl_xor_sync(0xffffffffu, den, 16);
    if (half == 0) {
        float rden = 1.f / den;
        float4 b = *(const float4*)&b2[fl * 4];
        float4 r;
        r.x = acc.x * rden + b.x;
        r.y = acc.y * rden + b.y;
        r.z = acc.z * rden + b.z;
        r.w = acc.w * rden + b.w;
        *(float4*)&g_z2[(size_t)w * 64 + fl * 4] = r;
    }
}

// ---------------- decode ----------------
__global__ void decode_kernel(const int* __restrict__ eli, int EL, float* __restrict__ out) {
    int t = blockIdx.x * blockDim.x + threadIdx.x;
    int g = t >> 4, li = t & 15;
    if (g >= EL) return;
    int a = eli[g];
    int b = eli[EL + g];
    float4 va = *(const float4*)&g_z2[(size_t)a * 64 + li * 4];
    float4 vb = *(const float4*)&g_z2[(size_t)b * 64 + li * 4];
    float s = va.x * vb.x + va.y * vb.y + va.z * vb.z + va.w * vb.w;
#pragma unroll
    for (int o = 8; o; o >>= 1) s += __shfl_down_sync(0xffffffffu, s, o, 16);
    if (li == 0) out[g] = s;
}

// ---------------- launcher (single stream, 8 launches) ----------------
extern "C" void kernel_launch(void* const* d_in, const int* in_sizes, int n_in,
                              void* d_out, int out_size) {
    const float* x    = (const float*)d_in[0];
    const int*   eidx = (const int*)d_in[1];
    const int*   eli  = (const int*)d_in[2];
    const float* W1   = (const float*)d_in[3];
    const float* as1v = (const float*)d_in[4];
    const float* ad1v = (const float*)d_in[5];
    const float* b1   = (const float*)d_in[6];
    const float* W2   = (const float*)d_in[7];
    const float* as2v = (const float*)d_in[8];
    const float* ad2v = (const float*)d_in[9];
    const float* b2   = (const float*)d_in[10];
    float* out = (float*)d_out;

    const int N  = in_sizes[0] / 128;
    const int E  = in_sizes[1] / 2;
    const int EL = in_sizes[2] / 2;
    const int* esrc = eidx;
    const int* edst = eidx + E;
    const int T = E + N;

    const int SM1 = (128 * 136 + 128 * 136) * 2 + 1024;
    const int SM2 = (128 * 136 + 128 * 72) * 2 + 1024;
    cudaFuncSetAttribute((mma_gemm_alpha_kernel<128>), cudaFuncAttributeMaxDynamicSharedMemorySize, SM1);
    cudaFuncSetAttribute((mma_gemm_alpha_kernel<64>),  cudaFuncAttributeMaxDynamicSharedMemorySize, SM2);

    void *pxh, *pw1h, *pw2h, *ph1h, *pz1h, *ph2h;
    float *pas1, *pad1, *pas2, *pad2;
    cudaGetSymbolAddress(&pxh,  g_xh);
    cudaGetSymbolAddress(&pw1h, g_w1h);
    cudaGetSymbolAddress(&pw2h, g_w2h);
    cudaGetSymbolAddress(&ph1h, g_h1h);
    cudaGetSymbolAddress(&pz1h, g_z1h);
    cudaGetSymbolAddress(&ph2h, g_h2h);
    cudaGetSymbolAddress((void**)&pas1, g_as1);
    cudaGetSymbolAddress((void**)&pad1, g_ad1);
    cudaGetSymbolAddress((void**)&pas2, g_as2);
    cudaGetSymbolAddress((void**)&pad2, g_ad2);

    const int B = 256;
    auto cdiv = [](long long a, long long b) { return (int)((a + b - 1) / b); };
    const int nb = cdiv(N, 1024);
    const int ntiles = cdiv(N, 64);
    const int ggrid = ntiles < 444 ? ntiles : 444;
    const int cvb = cdiv((long long)N * 128 + 128 * 192, (long long)B * 8);

    // 1) cvt + hist (+ ctr reset)
    misc_kernel<<<cvb + cdiv(T, B), B>>>(x, W1, W2, edst, E, N, cvb);
    // 2) single-pass scan (grid barrier)
    scan_kernel<<<nb, 1024>>>(N, T, nb);
    // 3) GEMM1 + alphas
    mma_gemm_alpha_kernel<128><<<ggrid, 256, SM1>>>((const __half*)pxh, (const __half*)pw1h,
                                                    (__half*)ph1h, as1v, ad1v, pas1, pad1, N, ntiles);
    // 4) scatter (profiler window)
    scatter_kernel<<<cdiv(T, B), B>>>(esrc, edst, E, N);
    // 5) layer1 aggregate
    agg1_kernel<<<cdiv(N, 8), 256>>>(b1, N);
    // 6) GEMM2 + alphas
    mma_gemm_alpha_kernel<64><<<ggrid, 256, SM2>>>((const __half*)pz1h, (const __half*)pw2h,
                                                   (__half*)ph2h, as2v, ad2v, pas2, pad2, N, ntiles);
    // 7) layer2 aggregate
    agg2_kernel<<<cdiv(N, 8), 256>>>(b2, N);
    // 8) decode
    decode_kernel<<<cdiv((long long)EL * 16, B), B>>>(eli, EL, out);
}

// round 17
// speedup vs baseline: 1.0497x; 1.0497x over previous
#include <cuda_runtime.h>
#include <cuda_fp16.h>
#include <cstdint>

#define MAXN 100000
#define MAXE 1600000

// ---------------- scratch (device globals; allocation-free) ----------------
__device__ __align__(16) __half g_xh[MAXN * 128];
__device__ __align__(16) __half g_w1h[128 * 128];
__device__ __align__(16) __half g_w2h[128 * 64];
__device__ __align__(16) __half g_h1h[MAXN * 128];
__device__ __align__(16) __half g_z1h[MAXN * 128];
__device__ __align__(16) __half g_h2h[MAXN * 64];
__device__ __align__(16) float g_z2[MAXN * 64];
__device__ __align__(8) float g_as1[MAXN * 2];
__device__ __align__(8) float g_ad1[MAXN * 2];
__device__ float g_as2[MAXN];
__device__ float g_ad2[MAXN];
__device__ __align__(16) int4 g_epk[MAXE + MAXN];
__device__ int g_deg[MAXN];          // zero at load; re-zeroed by scan1
__device__ int g_rowstart[MAXN + 1];
__device__ int g_cursor[MAXN];
__device__ int g_part[256];

// ---------------- helpers ----------------
__device__ __forceinline__ uint32_t smem_u32(const void* p) {
    uint32_t a;
    asm("{ .reg .u64 t; cvta.to.shared.u64 t, %1; cvt.u32.u64 %0, t; }" : "=r"(a) : "l"(p));
    return a;
}
__device__ __forceinline__ void ldsm4(uint32_t& r0, uint32_t& r1, uint32_t& r2, uint32_t& r3,
                                      uint32_t addr) {
    asm volatile("ldmatrix.sync.aligned.m8n8.x4.shared.b16 {%0,%1,%2,%3}, [%4];"
                 : "=r"(r0), "=r"(r1), "=r"(r2), "=r"(r3) : "r"(addr));
}
__device__ __forceinline__ void ldsm4t(uint32_t& r0, uint32_t& r1, uint32_t& r2, uint32_t& r3,
                                       uint32_t addr) {
    asm volatile("ldmatrix.sync.aligned.m8n8.x4.trans.shared.b16 {%0,%1,%2,%3}, [%4];"
                 : "=r"(r0), "=r"(r1), "=r"(r2), "=r"(r3) : "r"(addr));
}
__device__ __forceinline__ void mma16816(float* c, const uint32_t* a, const uint32_t* b) {
    asm volatile(
        "mma.sync.aligned.m16n8k16.row.col.f32.f16.f16.f32 "
        "{%0,%1,%2,%3}, {%4,%5,%6,%7}, {%8,%9}, {%0,%1,%2,%3};"
        : "+f"(c[0]), "+f"(c[1]), "+f"(c[2]), "+f"(c[3])
        : "r"(a[0]), "r"(a[1]), "r"(a[2]), "r"(a[3]), "r"(b[0]), "r"(b[1]));
}
__device__ __forceinline__ void cp_async16(uint32_t smem_addr, const void* gptr, bool valid) {
    int sz = valid ? 16 : 0;
    asm volatile("cp.async.ca.shared.global [%0], [%1], 16, %2;"
                 :: "r"(smem_addr), "l"(gptr), "r"(sz));
}

// ------- fused misc: blocks [0,cvb) cvt x/W1/W2 -> fp16 ; blocks [cvb,..) hist (2 edges/thr) -------
__global__ void misc_kernel(const float* __restrict__ x, const float* __restrict__ W1,
                            const float* __restrict__ W2,
                            const int* __restrict__ edst, int E, int N, int cvb) {
    int tid = threadIdx.x;
    if (blockIdx.x < cvb) {
        int nx = N * 128;
        int i = (blockIdx.x * blockDim.x + tid) * 8;
        int total = nx + 128 * 128 + 128 * 64;
        if (i >= total) return;
        const float* src;
        __half* dst;
        int off;
        if (i < nx)                  { src = x;  dst = g_xh;  off = i; }
        else if (i < nx + 128 * 128) { src = W1; dst = g_w1h; off = i - nx; }
        else                         { src = W2; dst = g_w2h; off = i - nx - 128 * 128; }
        float4 v0 = *(const float4*)&src[off];
        float4 v1 = *(const float4*)&src[off + 4];
        __half h[8];
        h[0] = __float2half_rn(v0.x); h[1] = __float2half_rn(v0.y);
        h[2] = __float2half_rn(v0.z); h[3] = __float2half_rn(v0.w);
        h[4] = __float2half_rn(v1.x); h[5] = __float2half_rn(v1.y);
        h[6] = __float2half_rn(v1.z); h[7] = __float2half_rn(v1.w);
        *(uint4*)&dst[off] = *(uint4*)h;
        return;
    }
    int t = ((blockIdx.x - cvb) * blockDim.x + tid) * 2;
#pragma unroll
    for (int u = 0; u < 2; u++) {
        int e = t + u;
        if (e < E + N) {
            int dst = (e < E) ? edst[e] : (e - E);
            atomicAdd(&g_deg[dst], 1);
        }
    }
}

// ---------------- CSR scans (R15) ----------------
__global__ void scan1_kernel(int N) {
    __shared__ int sm[1024];
    int i = blockIdx.x * 1024 + threadIdx.x;
    int v = (i < N) ? g_deg[i] : 0;
    sm[threadIdx.x] = v;
    __syncthreads();
#pragma unroll
    for (int o = 1; o < 1024; o <<= 1) {
        int t = 0;
        if (threadIdx.x >= o) t = sm[threadIdx.x - o];
        __syncthreads();
        if (threadIdx.x >= o) sm[threadIdx.x] += t;
        __syncthreads();
    }
    if (i < N) {
        g_rowstart[i] = sm[threadIdx.x] - v;
        g_deg[i] = 0;
    }
    if (threadIdx.x == 1023) g_part[blockIdx.x] = sm[1023];
}

__global__ void scan3_kernel(int N, int total, int nb) {
    __shared__ int sp[256];
    int tid = threadIdx.x;
    int pv = (tid < nb) ? g_part[tid] : 0;
    sp[tid] = pv;
    __syncthreads();
#pragma unroll
    for (int o = 1; o < 256; o <<= 1) {
        int t = 0;
        if (tid >= o) t = sp[tid - o];
        __syncthreads();
        if (tid >= o) sp[tid] += t;
        __syncthreads();
    }
    int i = blockIdx.x * blockDim.x + tid;
    if (i < N) {
        int b = i >> 10;
        int v = g_rowstart[i] + sp[b] - ((b < nb) ? g_part[b] : 0);
        g_rowstart[i] = v;
        g_cursor[i] = v;
    }
    if (i == 0) g_rowstart[N] = total;
}

// ---------------- scatter: 2 edges per thread (ILP) ----------------
__global__ void scatter_kernel(const int* __restrict__ esrc, const int* __restrict__ edst,
                               int E, int N) {
    int t = (blockIdx.x * blockDim.x + threadIdx.x) * 2;
    int srcs[2], dsts[2];
    bool val[2];
#pragma unroll
    for (int u = 0; u < 2; u++) {
        int e = t + u;
        val[u] = e < E + N;
        if (val[u]) {
            if (e < E) { srcs[u] = esrc[e]; dsts[u] = edst[e]; }
            else       { srcs[u] = dsts[u] = e - E; }
        }
    }
    float2 as[2], ad[2];
#pragma unroll
    for (int u = 0; u < 2; u++) {
        if (val[u]) {
            as[u] = *(const float2*)&g_as1[srcs[u] * 2];
            ad[u] = *(const float2*)&g_ad1[dsts[u] * 2];
        }
    }
    int pos[2];
#pragma unroll
    for (int u = 0; u < 2; u++)
        if (val[u]) pos[u] = atomicAdd(&g_cursor[dsts[u]], 1);
#pragma unroll
    for (int u = 0; u < 2; u++) {
        if (val[u]) {
            float v0 = as[u].x + ad[u].x, v1 = as[u].y + ad[u].y;
            v0 = v0 > 0.f ? v0 : 0.2f * v0;
            v1 = v1 > 0.f ? v1 : 0.2f * v1;
            g_epk[pos[u]] = make_int4(srcs[u], __float_as_int(__expf(v0)),
                                      __float_as_int(__expf(v1)), 0);
        }
    }
}

// ------- persistent tensor-core GEMM + alpha, 2x4 warp grid (R15) -------
template <int NC>
__global__ void __launch_bounds__(256, 3)
mma_gemm_alpha_kernel(const __half* __restrict__ Xh, const __half* __restrict__ Wh,
                      __half* __restrict__ Y,
                      const float* __restrict__ av_s, const float* __restrict__ av_d,
                      float* __restrict__ out_s, float* __restrict__ out_d,
                      int N, int ntiles) {
    extern __shared__ __half hsm[];
    constexpr int LDA = 136;
    constexpr int LDB = NC + 8;
    constexpr int NH = (NC == 128) ? 2 : 1;
    __half* Abuf[2] = { hsm, hsm + 64 * LDA };
    __half* Bs = hsm + 128 * LDA;
    float* sS = (float*)(Bs + 128 * LDB);
    float* sD = sS + 64 * NH;
    const int tid = threadIdx.x;
    constexpr int NT = NC / 32;
    constexpr int NSTRIP = (NC / 4) / 16;

    int t0 = blockIdx.x;
    if (t0 < ntiles) {
        int row0 = t0 * 64;
        for (int i = tid * 8; i < 64 * 128; i += 2048) {
            int r = i >> 7, c = i & 127;
            int gr = row0 + r;
            cp_async16(smem_u32(&Abuf[0][r * LDA + c]), Xh + (size_t)gr * 128 + c, gr < N);
        }
        asm volatile("cp.async.commit_group;");
    }
    for (int i = tid * 8; i < 128 * NC; i += 2048) {
        int r = i / NC, c = i % NC;
        *(uint4*)&Bs[r * LDB + c] = *(const uint4*)&Wh[i];
    }

    const int lane = tid & 31, wid = tid >> 5;
    const int wr = wid & 1;
    const int wcg = wid >> 1;
    const int r_base = wr * 32;
    const int c_base = wcg * (NC / 4);
    const int head = (NC == 128) ? (wcg >> 1) : 0;
    const int lr = lane & 15, lh = lane >> 4;
    const int row_in = lane >> 2;
    const int qc = (lane & 3) * 2;
    const uint32_t b_base = smem_u32(Bs);

    int it = 0;
    for (int j = t0; j < ntiles; j += gridDim.x, it++) {
        int jn = j + gridDim.x;
        __half* Acur = Abuf[it & 1];
        if (jn < ntiles) {
            __half* Anxt = Abuf[(it + 1) & 1];
            int row0n = jn * 64;
            for (int i = tid * 8; i < 64 * 128; i += 2048) {
                int r = i >> 7, c = i & 127;
                int gr = row0n + r;
                cp_async16(smem_u32(&Anxt[r * LDA + c]), Xh + (size_t)gr * 128 + c, gr < N);
            }
            asm volatile("cp.async.commit_group;");
            asm volatile("cp.async.wait_group 1;");
        } else {
            asm volatile("cp.async.wait_group 0;");
        }
        if (tid < 64 * NH) { sS[tid] = 0.f; sD[tid] = 0.f; }
        __syncthreads();

        const int row0 = j * 64;
        float c[2][NT][4];
#pragma unroll
        for (int mt = 0; mt < 2; mt++)
#pragma unroll
            for (int nt = 0; nt < NT; nt++)
#pragma unroll
                for (int q = 0; q < 4; q++) c[mt][nt][q] = 0.f;

        const uint32_t a_base = smem_u32(Acur);
#pragma unroll
        for (int kk = 0; kk < 8; kk++) {
            int k0 = kk * 16;
            uint32_t a[2][4];
#pragma unroll
            for (int mt = 0; mt < 2; mt++) {
                uint32_t addr = a_base + ((r_base + mt * 16 + lr) * LDA + k0 + lh * 8) * 2;
                ldsm4(a[mt][0], a[mt][1], a[mt][2], a[mt][3], addr);
            }
            uint32_t b[NT][2];
#pragma unroll
            for (int s = 0; s < NSTRIP; s++) {
                int n0 = c_base + s * 16;
                uint32_t addr = b_base + ((k0 + lr) * LDB + n0 + lh * 8) * 2;
                uint32_t r0, r1, r2, r3;
                ldsm4t(r0, r1, r2, r3, addr);
                b[2 * s][0] = r0; b[2 * s][1] = r1;
                b[2 * s + 1][0] = r2; b[2 * s + 1][1] = r3;
            }
#pragma unroll
            for (int mt = 0; mt < 2; mt++)
#pragma unroll
                for (int nt = 0; nt < NT; nt++) mma16816(c[mt][nt], a[mt], b[nt]);
        }

#pragma unroll
        for (int mt = 0; mt < 2; mt++) {
            int gr0 = row0 + r_base + mt * 16 + row_in;
            int gr1 = gr0 + 8;
            float ps0 = 0.f, pd0 = 0.f, ps1 = 0.f, pd1 = 0.f;
#pragma unroll
            for (int nt = 0; nt < NT; nt++) {
                int col = c_base + nt * 8 + qc;
                float avs0 = av_s[col], avs1 = av_s[col + 1];
                float avd0 = av_d[col], avd1 = av_d[col + 1];
                float* cc = c[mt][nt];
                ps0 = fmaf(cc[0], avs0, fmaf(cc[1], avs1, ps0));
                pd0 = fmaf(cc[0], avd0, fmaf(cc[1], avd1, pd0));
                ps1 = fmaf(cc[2], avs0, fmaf(cc[3], avs1, ps1));
                pd1 = fmaf(cc[2], avd0, fmaf(cc[3], avd1, pd1));
                if (gr0 < N) *(__half2*)&Y[(size_t)gr0 * NC + col] = __floats2half2_rn(cc[0], cc[1]);
                if (gr1 < N) *(__half2*)&Y[(size_t)gr1 * NC + col] = __floats2half2_rn(cc[2], cc[3]);
            }
#pragma unroll
            for (int o = 1; o <= 2; o <<= 1) {
                ps0 += __shfl_xor_sync(0xffffffffu, ps0, o);
                pd0 += __shfl_xor_sync(0xffffffffu, pd0, o);
                ps1 += __shfl_xor_sync(0xffffffffu, ps1, o);
                pd1 += __shfl_xor_sync(0xffffffffu, pd1, o);
            }
            if ((lane & 3) == 0) {
                int rl0 = (r_base + mt * 16 + row_in) * NH + head;
                int rl1 = rl0 + 8 * NH;
                atomicAdd(&sS[rl0], ps0);
                atomicAdd(&sD[rl0], pd0);
                atomicAdd(&sS[rl1], ps1);
                atomicAdd(&sD[rl1], pd1);
            }
        }
        __syncthreads();
        if (tid < 64 * NH) {
            int gr = row0 + tid / NH;
            if (gr < N) {
                out_s[(size_t)gr * NH + (tid % NH)] = sS[tid];
                out_d[(size_t)gr * NH + (tid % NH)] = sD[tid];
            }
        }
        __syncthreads();
    }
}

// ---------------- layer1 aggregate (R15: clamped loads) ----------------
__global__ void agg1_kernel(const float* __restrict__ b1, int N) {
    int w = blockIdx.x * 8 + (threadIdx.x >> 5);
    int lane = threadIdx.x & 31;
    if (w >= N) return;
    int s0 = g_rowstart[w], s1 = g_rowstart[w + 1];
    const int half = lane >> 4;
    const int fl = lane & 15;
    const bool h1sel = (fl >= 8);
    float acc[8];
#pragma unroll
    for (int k = 0; k < 8; k++) acc[k] = 0.f;
    float den0 = 0.f, den1 = 0.f;
    const int last = s1 - 1;

    for (int base = s0; base < s1; base += 8) {
        int4 pk[4];
#pragma unroll
        for (int q = 0; q < 4; q++) {
            int e = base + 2 * q + half;
            pk[q] = g_epk[min(e, last)];
        }
        uint4 uq[4];
#pragma unroll
        for (int q = 0; q < 4; q++)
            uq[q] = ((const uint4*)(g_h1h + (size_t)pk[q].x * 128))[fl];
#pragma unroll
        for (int q = 0; q < 4; q++) {
            bool valid = (base + 2 * q + half) < s1;
            float e0 = valid ? __int_as_float(pk[q].y) : 0.f;
            float e1 = valid ? __int_as_float(pk[q].z) : 0.f;
            den0 += e0; den1 += e1;
            float a = h1sel ? e1 : e0;
            __half2* ph = (__half2*)&uq[q];
#pragma unroll
            for (int p = 0; p < 4; p++) {
                float2 f = __half22float2(ph[p]);
                acc[2 * p]     = fmaf(a, f.x, acc[2 * p]);
                acc[2 * p + 1] = fmaf(a, f.y, acc[2 * p + 1]);
            }
        }
    }
#pragma unroll
    for (int k = 0; k < 8; k++) acc[k] += __shfl_xor_sync(0xffffffffu, acc[k], 16);
    den0 += __shfl_xor_sync(0xffffffffu, den0, 16);
    den1 += __shfl_xor_sync(0xffffffffu, den1, 16);
    if (half == 0) {
        float rden = 1.f / (h1sel ? den1 : den0);
        __half hb[8];
#pragma unroll
        for (int k = 0; k < 8; k++) {
            float v = acc[k] * rden + b1[fl * 8 + k];
            v = v > 0.f ? v : (__expf(v) - 1.f);
            hb[k] = __float2half_rn(v);
        }
        *(uint4*)&g_z1h[(size_t)w * 128 + fl * 8] = *(uint4*)hb;
    }
}

// ---------------- layer2 aggregate (R15: clamped loads) ----------------
__global__ void agg2_kernel(const float* __restrict__ b2, int N) {
    int w = blockIdx.x * 8 + (threadIdx.x >> 5);
    int lane = threadIdx.x & 31;
    if (w >= N) return;
    int s0 = g_rowstart[w], s1 = g_rowstart[w + 1];
    float add_d = g_ad2[w];
    const int half = lane >> 4;
    const int fl = lane & 15;
    float4 acc = make_float4(0.f, 0.f, 0.f, 0.f);
    float den = 0.f;
    const int last = s1 - 1;

    for (int base = s0; base < s1; base += 8) {
        int sq[4];
#pragma unroll
        for (int q = 0; q < 4; q++) {
            int e = base + 2 * q + half;
            sq[q] = g_epk[min(e, last)].x;
        }
        float asq[4];
#pragma unroll
        for (int q = 0; q < 4; q++) asq[q] = g_as2[sq[q]];
        uint2 uq[4];
#pragma unroll
        for (int q = 0; q < 4; q++) uq[q] = ((const uint2*)(g_h2h + (size_t)sq[q] * 64))[fl];
#pragma unroll
        for (int q = 0; q < 4; q++) {
            bool valid = (base + 2 * q + half) < s1;
            float v = asq[q] + add_d;
            v = v > 0.f ? v : 0.2f * v;
            float a = valid ? __expf(v) : 0.f;
            den += a;
            __half2* ph = (__half2*)&uq[q];
            float2 f0 = __half22float2(ph[0]);
            float2 f1 = __half22float2(ph[1]);
            acc.x = fmaf(a, f0.x, acc.x);
            acc.y = fmaf(a, f0.y, acc.y);
            acc.z = fmaf(a, f1.x, acc.z);
            acc.w = fmaf(a, f1.y, acc.w);
        }
    }
    acc.x += __shfl_xor_sync(0xffffffffu, acc.x, 16);
    acc.y += __shfl_xor_sync(0xffffffffu, acc.y, 16);
    acc.z += __shfl_xor_sync(0xffffffffu, acc.z, 16);
    acc.w += __shfl_xor_sync(0xffffffffu, acc.w, 16);
    den += __shfl_xor_sync(0xffffffffu, den, 16);
    if (half == 0) {
        float rden = 1.f / den;
        float4 b = *(const float4*)&b2[fl * 4];
        float4 r;
        r.x = acc.x * rden + b.x;
        r.y = acc.y * rden + b.y;
        r.z = acc.z * rden + b.z;
        r.w = acc.w * rden + b.w;
        *(float4*)&g_z2[(size_t)w * 64 + fl * 4] = r;
    }
}

// ---------------- decode ----------------
__global__ void decode_kernel(const int* __restrict__ eli, int EL, float* __restrict__ out) {
    int t = blockIdx.x * blockDim.x + threadIdx.x;
    int g = t >> 4, li = t & 15;
    if (g >= EL) return;
    int a = eli[g];
    int b = eli[EL + g];
    float4 va = *(const float4*)&g_z2[(size_t)a * 64 + li * 4];
    float4 vb = *(const float4*)&g_z2[(size_t)b * 64 + li * 4];
    float s = va.x * vb.x + va.y * vb.y + va.z * vb.z + va.w * vb.w;
#pragma unroll
    for (int o = 8; o; o >>= 1) s += __shfl_down_sync(0xffffffffu, s, o, 16);
    if (li == 0) out[g] = s;
}

// ---------------- launcher (single stream, 9 launches) ----------------
extern "C" void kernel_launch(void* const* d_in, const int* in_sizes, int n_in,
                              void* d_out, int out_size) {
    const float* x    = (const float*)d_in[0];
    const int*   eidx = (const int*)d_in[1];
    const int*   eli  = (const int*)d_in[2];
    const float* W1   = (const float*)d_in[3];
    const float* as1v = (const float*)d_in[4];
    const float* ad1v = (const float*)d_in[5];
    const float* b1   = (const float*)d_in[6];
    const float* W2   = (const float*)d_in[7];
    const float* as2v = (const float*)d_in[8];
    const float* ad2v = (const float*)d_in[9];
    const float* b2   = (const float*)d_in[10];
    float* out = (float*)d_out;

    const int N  = in_sizes[0] / 128;
    const int E  = in_sizes[1] / 2;
    const int EL = in_sizes[2] / 2;
    const int* esrc = eidx;
    const int* edst = eidx + E;
    const int T = E + N;

    const int SM1 = (128 * 136 + 128 * 136) * 2 + 1024;
    const int SM2 = (128 * 136 + 128 * 72) * 2 + 1024;
    cudaFuncSetAttribute((mma_gemm_alpha_kernel<128>), cudaFuncAttributeMaxDynamicSharedMemorySize, SM1);
    cudaFuncSetAttribute((mma_gemm_alpha_kernel<64>),  cudaFuncAttributeMaxDynamicSharedMemorySize, SM2);

    void *pxh, *pw1h, *pw2h, *ph1h, *pz1h, *ph2h;
    float *pas1, *pad1, *pas2, *pad2;
    cudaGetSymbolAddress(&pxh,  g_xh);
    cudaGetSymbolAddress(&pw1h, g_w1h);
    cudaGetSymbolAddress(&pw2h, g_w2h);
    cudaGetSymbolAddress(&ph1h, g_h1h);
    cudaGetSymbolAddress(&pz1h, g_z1h);
    cudaGetSymbolAddress(&ph2h, g_h2h);
    cudaGetSymbolAddress((void**)&pas1, g_as1);
    cudaGetSymbolAddress((void**)&pad1, g_ad1);
    cudaGetSymbolAddress((void**)&pas2, g_as2);
    cudaGetSymbolAddress((void**)&pad2, g_ad2);

    const int B = 256;
    auto cdiv = [](long long a, long long b) { return (int)((a + b - 1) / b); };
    const int nb = cdiv(N, 1024);
    const int ntiles = cdiv(N, 64);
    const int ggrid = ntiles < 444 ? ntiles : 444;
    const int cvb = cdiv((long long)N * 128 + 128 * 192, (long long)B * 8);

    // 1) fused cvt + hist
    misc_kernel<<<cvb + cdiv(T, (long long)B * 2), B>>>(x, W1, W2, edst, E, N, cvb);
    // 2-3) scans
    scan1_kernel<<<nb, 1024>>>(N);
    scan3_kernel<<<cdiv(N, B), B>>>(N, T, nb);
    // 4) GEMM1 + alphas (profiler window)
    mma_gemm_alpha_kernel<128><<<ggrid, 256, SM1>>>((const __half*)pxh, (const __half*)pw1h,
                                                    (__half*)ph1h, as1v, ad1v, pas1, pad1, N, ntiles);
    // 5) scatter (2 edges/thread)
    scatter_kernel<<<cdiv(T, (long long)B * 2), B>>>(esrc, edst, E, N);
    // 6) layer1 aggregate
    agg1_kernel<<<cdiv(N, 8), 256>>>(b1, N);
    // 7) GEMM2 + alphas
    mma_gemm_alpha_kernel<64><<<ggrid, 256, SM2>>>((const __half*)pz1h, (const __half*)pw2h,
                                                   (__half*)ph2h, as2v, ad2v, pas2, pad2, N, ntiles);
    // 8) layer2 aggregate
    agg2_kernel<<<cdiv(N, 8), 256>>>(b2, N);
    // 9) decode
    decode_kernel<<<cdiv((long long)EL * 16, B), B>>>(eli, EL, out);
}